// round 2
// baseline (speedup 1.0000x reference)
#include <cuda_runtime.h>
#include <math.h>

#define D_MODEL 256
#define HIDDEN  512
#define KSIZE   4
#define INNER   1024
#define BATCH   32
#define SEQ     2048
#define ROWS    (BATCH*SEQ)   // 65536
#define NCHUNK  32
#define CLEN    (SEQ/NCHUNK)  // 64

// ---------------- scratch (no cudaMalloc allowed) ----------------
__device__ float g_xh[(size_t)ROWS*HIDDEN];     // 128 MB
__device__ float g_z [(size_t)ROWS*HIDDEN];     // 128 MB
__device__ float g_xc[(size_t)ROWS*HIDDEN];     // 128 MB
__device__ float g_a [(size_t)ROWS*HIDDEN];     // 128 MB
__device__ float g_b [(size_t)ROWS*HIDDEN];     // 128 MB
__device__ float g_hs[(size_t)ROWS*D_MODEL];    // 64 MB
__device__ float g_big[(size_t)ROWS*2*HIDDEN];  // 256 MB (gates, then ff1)
__device__ float g_cA[(size_t)BATCH*NCHUNK*HIDDEN];    // 2 MB
__device__ float g_cB[(size_t)BATCH*NCHUNK*HIDDEN];    // 2 MB
__device__ float g_carry[(size_t)BATCH*NCHUNK*HIDDEN]; // 2 MB

__device__ __forceinline__ float sigmoidf_(float x) { return 1.f / (1.f + expf(-x)); }
__device__ __forceinline__ float siluf_(float x)    { return x / (1.f + expf(-x)); }

// ---------------- tiled fp32 SGEMM: C[M,N] = A[M,K] @ W[K,N] (+bias)(+silu) ----
#define BM 128
#define BN 128
#define BK 8
#define TM 8
#define TN 8

__global__ void __launch_bounds__(256)
sgemm_kernel(const float* __restrict__ A, const float* __restrict__ W,
             float* __restrict__ C, int N, int K,
             int lda, int ldw, int ldc,
             const float* __restrict__ bias, int act)
{
    __shared__ __align__(16) float As[BK][BM];
    __shared__ __align__(16) float Bs[BK][BN];

    const int tid = threadIdx.x;
    const int bx = blockIdx.x;   // N tile
    const int by = blockIdx.y;   // M tile

    const int a_row = tid >> 1;          // 0..127
    const int a_col = (tid & 1) << 2;    // 0 or 4
    const int b_row = tid >> 5;          // 0..7
    const int b_col = (tid & 31) << 2;   // 0..124 step 4

    const float* Aptr = A + (size_t)(by*BM + a_row) * lda + a_col;
    const float* Wptr = W + (size_t)b_row * ldw + (size_t)bx*BN + b_col;

    const int tx = tid & 15;   // col group
    const int ty = tid >> 4;   // row group

    float acc[TM][TN];
    #pragma unroll
    for (int i = 0; i < TM; i++)
        #pragma unroll
        for (int j = 0; j < TN; j++) acc[i][j] = 0.f;

    for (int k0 = 0; k0 < K; k0 += BK) {
        float4 av = *(const float4*)Aptr;
        As[a_col+0][a_row] = av.x;
        As[a_col+1][a_row] = av.y;
        As[a_col+2][a_row] = av.z;
        As[a_col+3][a_row] = av.w;
        *(float4*)&Bs[b_row][b_col] = *(const float4*)Wptr;
        __syncthreads();

        #pragma unroll
        for (int kk = 0; kk < BK; kk++) {
            float ar[TM], br[TN];
            *(float4*)&ar[0] = *(const float4*)&As[kk][ty*TM];
            *(float4*)&ar[4] = *(const float4*)&As[kk][ty*TM+4];
            *(float4*)&br[0] = *(const float4*)&Bs[kk][tx*TN];
            *(float4*)&br[4] = *(const float4*)&Bs[kk][tx*TN+4];
            #pragma unroll
            for (int i = 0; i < TM; i++)
                #pragma unroll
                for (int j = 0; j < TN; j++)
                    acc[i][j] = fmaf(ar[i], br[j], acc[i][j]);
        }
        __syncthreads();
        Aptr += BK;
        Wptr += (size_t)BK * ldw;
    }

    const int row0 = by*BM + ty*TM;
    const int col0 = bx*BN + tx*TN;
    #pragma unroll
    for (int i = 0; i < TM; i++) {
        float* cp = C + (size_t)(row0 + i) * ldc + col0;
        #pragma unroll
        for (int j = 0; j < TN; j += 4) {
            float4 v;
            v.x = acc[i][j+0]; v.y = acc[i][j+1]; v.z = acc[i][j+2]; v.w = acc[i][j+3];
            if (bias) {
                v.x += bias[col0+j+0]; v.y += bias[col0+j+1];
                v.z += bias[col0+j+2]; v.w += bias[col0+j+3];
            }
            if (act) {
                v.x = siluf_(v.x); v.y = siluf_(v.y); v.z = siluf_(v.z); v.w = siluf_(v.w);
            }
            *(float4*)(cp + j) = v;
        }
    }
}

// ---------------- depthwise causal conv (K=4) + bias + silu ----------------
__global__ void conv_kernel(const float* __restrict__ conv_w, const float* __restrict__ conv_b)
{
    size_t idx = (size_t)blockIdx.x * blockDim.x + threadIdx.x;
    if (idx >= (size_t)ROWS * HIDDEN) return;
    size_t row = idx >> 9;
    int c = (int)(idx & 511);
    int t = (int)(row & (SEQ - 1));
    const float* w = conv_w + c * KSIZE;
    float acc = conv_b[c];
    #pragma unroll
    for (int k = 0; k < KSIZE; k++) {
        int dt = t - (KSIZE - 1) + k;
        if (dt >= 0) acc = fmaf(g_xh[idx + (size_t)(k - (KSIZE-1)) * HIDDEN], w[k], acc);
    }
    g_xc[idx] = acc * sigmoidf_(acc);
}

// ---------------- gate elementwise: alpha, beta' ----------------
__global__ void gate_kernel(const float* __restrict__ Lambda)
{
    size_t idx = (size_t)blockIdx.x * blockDim.x + threadIdx.x;
    if (idx >= (size_t)ROWS * HIDDEN) return;
    size_t row = idx >> 9;
    int c = (int)(idx & 511);
    float rec = g_big[row * 1024 + c];
    float inp = g_big[row * 1024 + 512 + c];
    float sp = log1pf(expf(Lambda[c]));
    float alpha = expf(-sp * sigmoidf_(rec));
    float beta = sqrtf(fmaf(-alpha, alpha, 1.f + 1e-8f)) * sigmoidf_(inp);
    g_a[idx] = alpha;
    g_b[idx] = beta * g_xc[idx];
}

// ---------------- chunked scan, phase 1: per-chunk composition ----------------
// thread idx -> (batch, chunk, c). (A,B) = fold over t ascending: (A*a, a*B + b)
__global__ void scan_p1_kernel()
{
    int idx = blockIdx.x * blockDim.x + threadIdx.x;
    if (idx >= BATCH * NCHUNK * HIDDEN) return;
    int c = idx & 511;
    int rest = idx >> 9;
    int chunk = rest & (NCHUNK - 1);
    int b = rest / NCHUNK;
    size_t base = ((size_t)b * SEQ + (size_t)chunk * CLEN) * HIDDEN + c;
    float A = 1.f, Bv = 0.f;
    #pragma unroll 8
    for (int i = 0; i < CLEN; i++) {
        size_t off = base + (size_t)i * HIDDEN;
        float a = g_a[off];
        float bb = g_b[off];
        A *= a;
        Bv = fmaf(a, Bv, bb);
    }
    g_cA[idx] = A;
    g_cB[idx] = Bv;
}

// ---------------- phase 2: carry scan over chunks ----------------
__global__ void scan_p2_kernel()
{
    int idx = blockIdx.x * blockDim.x + threadIdx.x;   // (b, c)
    if (idx >= BATCH * HIDDEN) return;
    int c = idx & 511;
    int b = idx >> 9;
    float carry = 0.f;
    for (int chunk = 0; chunk < NCHUNK; chunk++) {
        int cidx = ((b * NCHUNK + chunk) << 9) + c;
        g_carry[cidx] = carry;
        carry = fmaf(g_cA[cidx], carry, g_cB[cidx]);
    }
}

// ---------------- phase 3: replay chunk from carry, fused silu(z)*h -> g_xh ---
__global__ void scan_p3_kernel()
{
    int idx = blockIdx.x * blockDim.x + threadIdx.x;
    if (idx >= BATCH * NCHUNK * HIDDEN) return;
    int c = idx & 511;
    int rest = idx >> 9;
    int chunk = rest & (NCHUNK - 1);
    int b = rest / NCHUNK;
    size_t base = ((size_t)b * SEQ + (size_t)chunk * CLEN) * HIDDEN + c;
    float h = g_carry[idx];
    #pragma unroll 4
    for (int i = 0; i < CLEN; i++) {
        size_t off = base + (size_t)i * HIDDEN;
        h = fmaf(g_a[off], h, g_b[off]);
        float z = g_z[off];
        g_xh[off] = siluf_(z) * h;
    }
}

// ---------------- LayerNorm over 256, warp-per-row, out = LN(a+b)*g + beta ---
__global__ void ln_kernel(const float* __restrict__ a, const float* __restrict__ b,
                          const float* __restrict__ gamma, const float* __restrict__ beta,
                          float* __restrict__ out)
{
    int warp = (int)((blockIdx.x * blockDim.x + threadIdx.x) >> 5);
    int lane = threadIdx.x & 31;
    if (warp >= ROWS) return;
    size_t base = (size_t)warp * D_MODEL;
    float v[8];
    float s = 0.f, s2 = 0.f;
    #pragma unroll
    for (int i = 0; i < 8; i++) {
        int col = lane + i * 32;
        float x = a[base + col] + b[base + col];
        v[i] = x;
        s += x;
        s2 = fmaf(x, x, s2);
    }
    #pragma unroll
    for (int o = 16; o; o >>= 1) {
        s  += __shfl_xor_sync(0xffffffffu, s,  o);
        s2 += __shfl_xor_sync(0xffffffffu, s2, o);
    }
    float mean = s * (1.f / D_MODEL);
    float var  = s2 * (1.f / D_MODEL) - mean * mean;
    float inv  = rsqrtf(var + 1e-12f);
    #pragma unroll
    for (int i = 0; i < 8; i++) {
        int col = lane + i * 32;
        out[base + col] = (v[i] - mean) * inv * gamma[col] + beta[col];
    }
}

// ---------------- launcher ----------------
extern "C" void kernel_launch(void* const* d_in, const int* in_sizes, int n_in,
                              void* d_out, int out_size)
{
    const float* x       = (const float*)d_in[0];
    const float* w_in    = (const float*)d_in[1];
    const float* conv_w  = (const float*)d_in[2];
    const float* conv_b  = (const float*)d_in[3];
    const float* w_gates = (const float*)d_in[4];
    const float* b_gates = (const float*)d_in[5];
    const float* Lambda  = (const float*)d_in[6];
    const float* w_out   = (const float*)d_in[7];
    const float* ln1_g   = (const float*)d_in[8];
    const float* ln1_b   = (const float*)d_in[9];
    const float* ffn_w1  = (const float*)d_in[10];
    const float* ffn_b1  = (const float*)d_in[11];
    const float* ffn_w2  = (const float*)d_in[12];
    const float* ffn_b2  = (const float*)d_in[13];
    const float* ln2_g   = (const float*)d_in[14];
    const float* ln2_b   = (const float*)d_in[15];
    float* out = (float*)d_out;

    float *p_xh, *p_xc, *p_hs, *p_big;
    cudaGetSymbolAddress((void**)&p_xh,  g_xh);
    cudaGetSymbolAddress((void**)&p_xc,  g_xc);
    cudaGetSymbolAddress((void**)&p_hs,  g_hs);
    cudaGetSymbolAddress((void**)&p_big, g_big);
    float *p_z;
    cudaGetSymbolAddress((void**)&p_z, g_z);

    const int ew_blocks = (int)(((size_t)ROWS * HIDDEN + 255) / 256);
    const int ch_blocks = (BATCH * NCHUNK * HIDDEN + 255) / 256;

    // 1. xh = x @ w_in[:, :512] ; z = x @ w_in[:, 512:]
    {
        dim3 grid(HIDDEN / BN, ROWS / BM);
        sgemm_kernel<<<grid, 256>>>(x, w_in,        p_xh, HIDDEN, D_MODEL, D_MODEL, 2*HIDDEN, HIDDEN, nullptr, 0);
        sgemm_kernel<<<grid, 256>>>(x, w_in+HIDDEN, p_z,  HIDDEN, D_MODEL, D_MODEL, 2*HIDDEN, HIDDEN, nullptr, 0);
    }
    // 2. xc = silu(conv(xh) + conv_b)
    conv_kernel<<<ew_blocks, 256>>>(conv_w, conv_b);
    // 3. gates = xc @ w_gates + b_gates
    {
        dim3 grid(2*HIDDEN / BN, ROWS / BM);
        sgemm_kernel<<<grid, 256>>>(p_xc, w_gates, p_big, 2*HIDDEN, HIDDEN, HIDDEN, 2*HIDDEN, 2*HIDDEN, b_gates, 0);
    }
    // 4. alpha -> g_a, beta' -> g_b
    gate_kernel<<<ew_blocks, 256>>>(Lambda);
    // 5. chunked scan + fused silu(z)*h -> g_xh
    scan_p1_kernel<<<ch_blocks, 256>>>();
    scan_p2_kernel<<<(BATCH*HIDDEN + 255)/256, 256>>>();
    scan_p3_kernel<<<ch_blocks, 256>>>();
    // 6. rec_out = (silu(z)*h) @ w_out -> g_hs
    {
        dim3 grid(D_MODEL / BN, ROWS / BM);
        sgemm_kernel<<<grid, 256>>>(p_xh, w_out, p_hs, D_MODEL, HIDDEN, HIDDEN, D_MODEL, D_MODEL, nullptr, 0);
    }
    // 7. hs = LN(rec_out + x)
    ln_kernel<<<ROWS/8, 256>>>(p_hs, x, ln1_g, ln1_b, p_hs);
    // 8. ff1 = silu(hs @ ffn_w1 + b1) -> g_big
    {
        dim3 grid(INNER / BN, ROWS / BM);
        sgemm_kernel<<<grid, 256>>>(p_hs, ffn_w1, p_big, INNER, D_MODEL, D_MODEL, INNER, INNER, ffn_b1, 1);
    }
    // 9. ff = ff1 @ ffn_w2 + b2 -> g_xc
    {
        dim3 grid(D_MODEL / BN, ROWS / BM);
        sgemm_kernel<<<grid, 256>>>(p_big, ffn_w2, p_xc, D_MODEL, INNER, INNER, D_MODEL, D_MODEL, ffn_b2, 0);
    }
    // 10. out = LN(ff + hs)
    ln_kernel<<<ROWS/8, 256>>>(p_xc, p_hs, ln2_g, ln2_b, out);
}

// round 4
// speedup vs baseline: 1.6022x; 1.6022x over previous
#include <cuda_runtime.h>
#include <cuda_bf16.h>
#include <math.h>
#include <cstdint>

#define D_MODEL 256
#define HIDDEN  512
#define KSIZE   4
#define INNER   1024
#define BATCH   32
#define SEQ     2048
#define ROWS    (BATCH*SEQ)   // 65536
#define NCHUNK  32
#define CLEN    (SEQ/NCHUNK)  // 64

typedef __nv_bfloat16 bf16;

// ---------------- scratch ----------------
__device__ float g_xz   [(size_t)ROWS*1024];   // xh | z
__device__ float g_gates[(size_t)ROWS*1024];   // rec | inp
__device__ float g_a    [(size_t)ROWS*512];
__device__ float g_b    [(size_t)ROWS*512];
__device__ float g_rec  [(size_t)ROWS*256];
__device__ float g_hs   [(size_t)ROWS*256];
__device__ float g_ff   [(size_t)ROWS*256];
__device__ bf16  g_x_hi [(size_t)ROWS*256];
__device__ bf16  g_x_lo [(size_t)ROWS*256];
__device__ bf16  g_xc_hi[(size_t)ROWS*512];
__device__ bf16  g_xc_lo[(size_t)ROWS*512];
__device__ bf16  g_u_hi [(size_t)ROWS*512];
__device__ bf16  g_u_lo [(size_t)ROWS*512];
__device__ bf16  g_hs_hi[(size_t)ROWS*256];
__device__ bf16  g_hs_lo[(size_t)ROWS*256];
__device__ bf16  g_f1_hi[(size_t)ROWS*1024];
__device__ bf16  g_f1_lo[(size_t)ROWS*1024];
__device__ float g_cA[(size_t)BATCH*NCHUNK*512];
__device__ float g_cB[(size_t)BATCH*NCHUNK*512];
__device__ float g_cr[(size_t)BATCH*NCHUNK*512];
// transposed split weights [N, K]
__device__ bf16 g_wtin_hi[1024*256], g_wtin_lo[1024*256];
__device__ bf16 g_wtg_hi [1024*512], g_wtg_lo [1024*512];
__device__ bf16 g_wto_hi [256*512],  g_wto_lo [256*512];
__device__ bf16 g_wtf1_hi[1024*256], g_wtf1_lo[1024*256];
__device__ bf16 g_wtf2_hi[256*1024], g_wtf2_lo[256*1024];

__device__ __forceinline__ float sigmoidf_(float x) { return 1.f / (1.f + expf(-x)); }
__device__ __forceinline__ float siluf_(float x)    { return x / (1.f + expf(-x)); }

__device__ __forceinline__ uint32_t smem_u32(const void* p) {
    uint32_t a;
    asm("{ .reg .u64 t; cvta.to.shared.u64 t, %1; cvt.u32.u64 %0, t; }" : "=r"(a) : "l"(p));
    return a;
}
__device__ __forceinline__ void ldsm_x4(uint32_t* r, uint32_t addr) {
    asm volatile("ldmatrix.sync.aligned.m8n8.x4.shared.b16 {%0,%1,%2,%3}, [%4];"
                 : "=r"(r[0]), "=r"(r[1]), "=r"(r[2]), "=r"(r[3]) : "r"(addr));
}
__device__ __forceinline__ void mma16816(float* c, const uint32_t* a, const uint32_t* b) {
    asm volatile("mma.sync.aligned.m16n8k16.row.col.f32.bf16.bf16.f32 "
                 "{%0,%1,%2,%3}, {%4,%5,%6,%7}, {%8,%9}, {%0,%1,%2,%3};"
                 : "+f"(c[0]), "+f"(c[1]), "+f"(c[2]), "+f"(c[3])
                 : "r"(a[0]), "r"(a[1]), "r"(a[2]), "r"(a[3]), "r"(b[0]), "r"(b[1]));
}

// ---------------- mma.sync GEMM: C[M,N] = (Ahi+Alo)[M,K] @ (Bhi+Blo)[N,K]^T ----
// block 128x128x32, 8 warps (4x2), warp tile 32x64, bf16 hi/lo 3-MMA split.
#define BM 128
#define BN 128
#define BK 32
#define PAD_LD 40   // smem row stride in bf16 (conflict-free for ldmatrix)

__global__ void __launch_bounds__(256, 1)
gemm_mma(const bf16* __restrict__ Ahi, const bf16* __restrict__ Alo,
         const bf16* __restrict__ Bhi, const bf16* __restrict__ Blo,
         int K, float* __restrict__ Cf, bf16* __restrict__ Chi, bf16* __restrict__ Clo,
         int ldc, const float* __restrict__ bias, int act)
{
    __shared__ __align__(16) bf16 sAh[BM][PAD_LD];
    __shared__ __align__(16) bf16 sAl[BM][PAD_LD];
    __shared__ __align__(16) bf16 sBh[BN][PAD_LD];
    __shared__ __align__(16) bf16 sBl[BN][PAD_LD];

    const int tid = threadIdx.x, wid = tid >> 5, lane = tid & 31;
    const int bx = blockIdx.x, by = blockIdx.y;
    const int warp_m = wid & 3, warp_n = wid >> 2;

    const bf16* gAh = Ahi + (size_t)(by * BM) * K;
    const bf16* gAl = Alo + (size_t)(by * BM) * K;
    const bf16* gBh = Bhi + (size_t)(bx * BN) * K;
    const bf16* gBl = Blo + (size_t)(bx * BN) * K;

    const uint32_t baseAh = smem_u32(&sAh[0][0]);
    const uint32_t baseAl = smem_u32(&sAl[0][0]);
    const uint32_t baseBh = smem_u32(&sBh[0][0]);
    const uint32_t baseBl = smem_u32(&sBl[0][0]);

    float c[2][8][4];
    #pragma unroll
    for (int mt = 0; mt < 2; mt++)
        #pragma unroll
        for (int nt = 0; nt < 8; nt++)
            #pragma unroll
            for (int j = 0; j < 4; j++) c[mt][nt][j] = 0.f;

    // ldmatrix per-lane address offsets (in bf16 elements), computed once
    const int a_row = (lane & 15);             // + m0
    const int a_kof = (lane >> 4) * 8;         // + ks*16
    const int b_rof = ((lane >> 4) & 1) * 8 + (lane & 7);  // + n0
    const int b_kof = ((lane >> 3) & 1) * 8;   // + ks*16

    const int nchunk = K / BK;
    for (int ch = 0; ch < nchunk; ch++) {
        const int k0 = ch * BK;
        // load tiles: 512 uint4 slots per matrix, 2 per thread
        #pragma unroll
        for (int l = 0; l < 2; l++) {
            int s = tid + l * 256;
            int row = s >> 2, kg = s & 3;
            size_t goff = (size_t)row * K + k0 + kg * 8;
            int soff = kg * 8;
            *(uint4*)&sAh[row][soff] = *(const uint4*)(gAh + goff);
            *(uint4*)&sAl[row][soff] = *(const uint4*)(gAl + goff);
            *(uint4*)&sBh[row][soff] = *(const uint4*)(gBh + goff);
            *(uint4*)&sBl[row][soff] = *(const uint4*)(gBl + goff);
        }
        __syncthreads();

        #pragma unroll
        for (int ks = 0; ks < 2; ks++) {
            const int kc = ks * 16;
            uint32_t ah[2][4], al[2][4];
            #pragma unroll
            for (int mt = 0; mt < 2; mt++) {
                int row = warp_m * 32 + mt * 16 + a_row;
                uint32_t off = (uint32_t)(row * PAD_LD + kc + a_kof) * 2;
                ldsm_x4(ah[mt], baseAh + off);
                ldsm_x4(al[mt], baseAl + off);
            }
            uint32_t bh[8][2], bl[8][2];
            #pragma unroll
            for (int np = 0; np < 4; np++) {
                int rown = warp_n * 64 + np * 16 + b_rof;
                uint32_t off = (uint32_t)(rown * PAD_LD + kc + b_kof) * 2;
                uint32_t r[4];
                ldsm_x4(r, baseBh + off);
                bh[np*2][0] = r[0]; bh[np*2][1] = r[1];
                bh[np*2+1][0] = r[2]; bh[np*2+1][1] = r[3];
                ldsm_x4(r, baseBl + off);
                bl[np*2][0] = r[0]; bl[np*2][1] = r[1];
                bl[np*2+1][0] = r[2]; bl[np*2+1][1] = r[3];
            }
            #pragma unroll
            for (int mt = 0; mt < 2; mt++)
                #pragma unroll
                for (int nt = 0; nt < 8; nt++) {
                    mma16816(c[mt][nt], ah[mt], bh[nt]);
                    mma16816(c[mt][nt], al[mt], bh[nt]);
                    mma16816(c[mt][nt], ah[mt], bl[nt]);
                }
        }
        __syncthreads();
    }

    // epilogue
    const int row00 = by * BM + warp_m * 32 + (lane >> 2);
    const int col00 = bx * BN + warp_n * 64 + (lane & 3) * 2;
    #pragma unroll
    for (int mt = 0; mt < 2; mt++) {
        #pragma unroll
        for (int nt = 0; nt < 8; nt++) {
            const int col = col00 + nt * 8;
            #pragma unroll
            for (int half = 0; half < 2; half++) {
                const int row = row00 + mt * 16 + half * 8;
                float v0 = c[mt][nt][half*2+0];
                float v1 = c[mt][nt][half*2+1];
                if (bias) { v0 += bias[col]; v1 += bias[col+1]; }
                if (act)  { v0 = siluf_(v0); v1 = siluf_(v1); }
                if (Cf) {
                    float2 q; q.x = v0; q.y = v1;
                    *(float2*)(Cf + (size_t)row * ldc + col) = q;
                } else {
                    bf16 h0 = __float2bfloat16(v0);
                    bf16 h1 = __float2bfloat16(v1);
                    bf16 l0 = __float2bfloat16(v0 - __bfloat162float(h0));
                    bf16 l1 = __float2bfloat16(v1 - __bfloat162float(h1));
                    __nv_bfloat162 hp; hp.x = h0; hp.y = h1;
                    __nv_bfloat162 lp; lp.x = l0; lp.y = l1;
                    *(__nv_bfloat162*)(Chi + (size_t)row * ldc + col) = hp;
                    *(__nv_bfloat162*)(Clo + (size_t)row * ldc + col) = lp;
                }
            }
        }
    }
}

// ---------------- weight prep: T[n,k] = W[k,n], split hi/lo ----------------
__global__ void wprep_kernel(const float* __restrict__ W, int K, int N,
                             bf16* __restrict__ Thi, bf16* __restrict__ Tlo)
{
    int idx = blockIdx.x * blockDim.x + threadIdx.x;
    if (idx >= N * K) return;
    int n = idx / K, k = idx - n * K;
    float v = W[(size_t)k * N + n];
    bf16 hi = __float2bfloat16(v);
    Thi[idx] = hi;
    Tlo[idx] = __float2bfloat16(v - __bfloat162float(hi));
}

// ---------------- convert x -> hi/lo ----------------
__global__ void xsplit_kernel(const float* __restrict__ x)
{
    size_t idx = (size_t)blockIdx.x * blockDim.x + threadIdx.x;
    if (idx >= (size_t)ROWS * 256) return;
    float v = x[idx];
    bf16 hi = __float2bfloat16(v);
    g_x_hi[idx] = hi;
    g_x_lo[idx] = __float2bfloat16(v - __bfloat162float(hi));
}

// ---------------- conv (K=4) + bias + silu -> xc hi/lo ----------------
__global__ void conv_kernel(const float* __restrict__ conv_w, const float* __restrict__ conv_b)
{
    size_t idx = (size_t)blockIdx.x * blockDim.x + threadIdx.x;
    if (idx >= (size_t)ROWS * 512) return;
    size_t row = idx >> 9;
    int c = (int)(idx & 511);
    int t = (int)(row & (SEQ - 1));
    const float* w = conv_w + c * KSIZE;
    const float* xb = g_xz + row * 1024 + c;
    float acc = conv_b[c];
    if (t >= 3) {
        acc = fmaf(xb[-3*1024], w[0], acc);
        acc = fmaf(xb[-2*1024], w[1], acc);
        acc = fmaf(xb[-1*1024], w[2], acc);
        acc = fmaf(xb[0],       w[3], acc);
    } else {
        #pragma unroll
        for (int k = 0; k < KSIZE; k++)
            if (t - (KSIZE-1) + k >= 0) acc = fmaf(xb[(ptrdiff_t)(k - (KSIZE-1)) * 1024], w[k], acc);
    }
    float s = acc * sigmoidf_(acc);
    bf16 hi = __float2bfloat16(s);
    g_xc_hi[idx] = hi;
    g_xc_lo[idx] = __float2bfloat16(s - __bfloat162float(hi));
}

// ---------------- gates -> alpha, beta' ----------------
__global__ void gate_kernel(const float* __restrict__ Lambda)
{
    size_t idx = (size_t)blockIdx.x * blockDim.x + threadIdx.x;
    if (idx >= (size_t)ROWS * 512) return;
    size_t row = idx >> 9;
    int c = (int)(idx & 511);
    float rec = g_gates[row * 1024 + c];
    float inp = g_gates[row * 1024 + 512 + c];
    float xc = __bfloat162float(g_xc_hi[idx]) + __bfloat162float(g_xc_lo[idx]);
    float sp = log1pf(expf(Lambda[c]));
    float alpha = expf(-sp * sigmoidf_(rec));
    float beta = sqrtf(fmaf(-alpha, alpha, 1.f + 1e-8f)) * sigmoidf_(inp);
    g_a[idx] = alpha;
    g_b[idx] = beta * xc;
}

// ---------------- chunked scan ----------------
__global__ void scan_p1_kernel()
{
    int idx = blockIdx.x * blockDim.x + threadIdx.x;
    if (idx >= BATCH * NCHUNK * 512) return;
    int c = idx & 511;
    int rest = idx >> 9;
    int chunk = rest & (NCHUNK - 1);
    int b = rest / NCHUNK;
    size_t base = ((size_t)b * SEQ + (size_t)chunk * CLEN) * 512 + c;
    float A = 1.f, Bv = 0.f;
    #pragma unroll 8
    for (int i = 0; i < CLEN; i++) {
        size_t off = base + (size_t)i * 512;
        float a = g_a[off], bb = g_b[off];
        A *= a;
        Bv = fmaf(a, Bv, bb);
    }
    g_cA[idx] = A;
    g_cB[idx] = Bv;
}
__global__ void scan_p2_kernel()
{
    int idx = blockIdx.x * blockDim.x + threadIdx.x;
    if (idx >= BATCH * 512) return;
    int c = idx & 511;
    int b = idx >> 9;
    float carry = 0.f;
    for (int chunk = 0; chunk < NCHUNK; chunk++) {
        int cidx = ((b * NCHUNK + chunk) << 9) + c;
        g_cr[cidx] = carry;
        carry = fmaf(g_cA[cidx], carry, g_cB[cidx]);
    }
}
__global__ void scan_p3_kernel()
{
    int idx = blockIdx.x * blockDim.x + threadIdx.x;
    if (idx >= BATCH * NCHUNK * 512) return;
    int c = idx & 511;
    int rest = idx >> 9;
    int chunk = rest & (NCHUNK - 1);
    int b = rest / NCHUNK;
    size_t rowbase = (size_t)b * SEQ + (size_t)chunk * CLEN;
    size_t base = rowbase * 512 + c;
    const float* zp = g_xz + rowbase * 1024 + 512 + c;
    float h = g_cr[idx];
    #pragma unroll 4
    for (int i = 0; i < CLEN; i++) {
        size_t off = base + (size_t)i * 512;
        h = fmaf(g_a[off], h, g_b[off]);
        float z = zp[(size_t)i * 1024];
        float u = siluf_(z) * h;
        bf16 hi = __float2bfloat16(u);
        g_u_hi[off] = hi;
        g_u_lo[off] = __float2bfloat16(u - __bfloat162float(hi));
    }
}

// ---------------- LayerNorm(a+b), optional bf16 pair out ----------------
__global__ void ln_kernel(const float* __restrict__ a, const float* __restrict__ b,
                          const float* __restrict__ gamma, const float* __restrict__ beta,
                          float* __restrict__ out, bf16* __restrict__ ohi, bf16* __restrict__ olo)
{
    int warp = (int)((blockIdx.x * blockDim.x + threadIdx.x) >> 5);
    int lane = threadIdx.x & 31;
    if (warp >= ROWS) return;
    size_t base = (size_t)warp * 256;
    float v[8];
    float s = 0.f, s2 = 0.f;
    #pragma unroll
    for (int i = 0; i < 8; i++) {
        int col = lane + i * 32;
        float x = a[base + col] + b[base + col];
        v[i] = x;
        s += x;
        s2 = fmaf(x, x, s2);
    }
    #pragma unroll
    for (int o = 16; o; o >>= 1) {
        s  += __shfl_xor_sync(0xffffffffu, s,  o);
        s2 += __shfl_xor_sync(0xffffffffu, s2, o);
    }
    float mean = s * (1.f / 256.f);
    float var  = s2 * (1.f / 256.f) - mean * mean;
    float inv  = rsqrtf(var + 1e-12f);
    #pragma unroll
    for (int i = 0; i < 8; i++) {
        int col = lane + i * 32;
        float y = (v[i] - mean) * inv * gamma[col] + beta[col];
        out[base + col] = y;
        if (ohi) {
            bf16 hi = __float2bfloat16(y);
            ohi[base + col] = hi;
            olo[base + col] = __float2bfloat16(y - __bfloat162float(hi));
        }
    }
}

// ---------------- launcher ----------------
extern "C" void kernel_launch(void* const* d_in, const int* in_sizes, int n_in,
                              void* d_out, int out_size)
{
    const float* x       = (const float*)d_in[0];
    const float* w_in    = (const float*)d_in[1];
    const float* conv_w  = (const float*)d_in[2];
    const float* conv_b  = (const float*)d_in[3];
    const float* w_gates = (const float*)d_in[4];
    const float* b_gates = (const float*)d_in[5];
    const float* Lambda  = (const float*)d_in[6];
    const float* w_out   = (const float*)d_in[7];
    const float* ln1_g   = (const float*)d_in[8];
    const float* ln1_b   = (const float*)d_in[9];
    const float* ffn_w1  = (const float*)d_in[10];
    const float* ffn_b1  = (const float*)d_in[11];
    const float* ffn_w2  = (const float*)d_in[12];
    const float* ffn_b2  = (const float*)d_in[13];
    const float* ln2_g   = (const float*)d_in[14];
    const float* ln2_b   = (const float*)d_in[15];
    float* out = (float*)d_out;

    #define SYM(p, s) float* p; cudaGetSymbolAddress((void**)&p, s)
    #define SYMB(p, s) bf16* p; cudaGetSymbolAddress((void**)&p, s)
    SYM(p_xz, g_xz);   SYM(p_gates, g_gates);
    SYM(p_rec, g_rec); SYM(p_hs, g_hs); SYM(p_ff, g_ff);
    SYMB(p_xhi, g_x_hi);  SYMB(p_xlo, g_x_lo);
    SYMB(p_xchi, g_xc_hi); SYMB(p_xclo, g_xc_lo);
    SYMB(p_uhi, g_u_hi);   SYMB(p_ulo, g_u_lo);
    SYMB(p_hshi, g_hs_hi); SYMB(p_hslo, g_hs_lo);
    SYMB(p_f1hi, g_f1_hi); SYMB(p_f1lo, g_f1_lo);
    SYMB(p_wtin_hi, g_wtin_hi); SYMB(p_wtin_lo, g_wtin_lo);
    SYMB(p_wtg_hi,  g_wtg_hi);  SYMB(p_wtg_lo,  g_wtg_lo);
    SYMB(p_wto_hi,  g_wto_hi);  SYMB(p_wto_lo,  g_wto_lo);
    SYMB(p_wtf1_hi, g_wtf1_hi); SYMB(p_wtf1_lo, g_wtf1_lo);
    SYMB(p_wtf2_hi, g_wtf2_hi); SYMB(p_wtf2_lo, g_wtf2_lo);

    const int ew512 = (int)(((size_t)ROWS * 512 + 255) / 256);
    const int ew256 = (int)(((size_t)ROWS * 256 + 255) / 256);
    const int ch_blocks = (BATCH * NCHUNK * 512 + 255) / 256;

    // weight prep (W is [K,N] row-major; output T[N][K])
    wprep_kernel<<<(1024*256+255)/256, 256>>>(w_in,    256,  1024, p_wtin_hi, p_wtin_lo);
    wprep_kernel<<<(1024*512+255)/256, 256>>>(w_gates, 512,  1024, p_wtg_hi,  p_wtg_lo);
    wprep_kernel<<<(256*512 +255)/256, 256>>>(w_out,   512,  256,  p_wto_hi,  p_wto_lo);
    wprep_kernel<<<(1024*256+255)/256, 256>>>(ffn_w1,  256,  1024, p_wtf1_hi, p_wtf1_lo);
    wprep_kernel<<<(256*1024+255)/256, 256>>>(ffn_w2,  1024, 256,  p_wtf2_hi, p_wtf2_lo);
    xsplit_kernel<<<ew256, 256>>>(x);

    const dim3 gN1024(1024 / BN, ROWS / BM);
    const dim3 gN256 (256  / BN, ROWS / BM);

    // GEMM1: xz = x @ w_in   [65536,1024], K=256
    gemm_mma<<<gN1024, 256>>>(p_xhi, p_xlo, p_wtin_hi, p_wtin_lo, 256,
                              p_xz, nullptr, nullptr, 1024, nullptr, 0);
    conv_kernel<<<ew512, 256>>>(conv_w, conv_b);
    // GEMM2: gates = xc @ w_gates + b_gates  [65536,1024], K=512
    gemm_mma<<<gN1024, 256>>>(p_xchi, p_xclo, p_wtg_hi, p_wtg_lo, 512,
                              p_gates, nullptr, nullptr, 1024, b_gates, 0);
    gate_kernel<<<ew512, 256>>>(Lambda);
    scan_p1_kernel<<<ch_blocks, 256>>>();
    scan_p2_kernel<<<(BATCH*512 + 255)/256, 256>>>();
    scan_p3_kernel<<<ch_blocks, 256>>>();
    // GEMM3: rec = u @ w_out  [65536,256], K=512
    gemm_mma<<<gN256, 256>>>(p_uhi, p_ulo, p_wto_hi, p_wto_lo, 512,
                             p_rec, nullptr, nullptr, 256, nullptr, 0);
    // LN1: hs = LN(rec + x), also emit bf16 pair
    ln_kernel<<<ROWS/8, 256>>>(p_rec, x, ln1_g, ln1_b, p_hs, p_hshi, p_hslo);
    // GEMM4: f1 = silu(hs @ ffn_w1 + b1) -> bf16 pair  [65536,1024], K=256
    gemm_mma<<<gN1024, 256>>>(p_hshi, p_hslo, p_wtf1_hi, p_wtf1_lo, 256,
                              nullptr, p_f1hi, p_f1lo, 1024, ffn_b1, 1);
    // GEMM5: ff = f1 @ ffn_w2 + b2  [65536,256], K=1024
    gemm_mma<<<gN256, 256>>>(p_f1hi, p_f1lo, p_wtf2_hi, p_wtf2_lo, 1024,
                             p_ff, nullptr, nullptr, 256, ffn_b2, 0);
    // LN2: out = LN(ff + hs)
    ln_kernel<<<ROWS/8, 256>>>(p_ff, p_hs, ln2_g, ln2_b, out, nullptr, nullptr);
}

// round 6
// speedup vs baseline: 2.4156x; 1.5076x over previous
#include <cuda_runtime.h>
#include <cuda_fp16.h>
#include <math.h>
#include <cstdint>

#define D_MODEL 256
#define HIDDEN  512
#define KSIZE   4
#define INNER   1024
#define BATCH   32
#define SEQ     2048
#define ROWS    (BATCH*SEQ)   // 65536
#define NCHUNK  32
#define CLEN    (SEQ/NCHUNK)  // 64

typedef __half h16;

// ---------------- scratch ----------------
__device__ h16   g_xz   [(size_t)ROWS*1024];   // xh | z (fp16)
__device__ float g_gates[(size_t)ROWS*1024];   // rec | inp (fp32: alpha precision)
__device__ float g_a    [(size_t)ROWS*512];
__device__ float g_b    [(size_t)ROWS*512];
__device__ h16   g_xc   [(size_t)ROWS*512];
__device__ h16   g_u    [(size_t)ROWS*512];
__device__ h16   g_x16  [(size_t)ROWS*256];
__device__ float g_rec  [(size_t)ROWS*256];
__device__ float g_hs   [(size_t)ROWS*256];
__device__ h16   g_hs16 [(size_t)ROWS*256];
__device__ h16   g_f1   [(size_t)ROWS*1024];
__device__ float g_ff   [(size_t)ROWS*256];
__device__ float g_cA[(size_t)BATCH*NCHUNK*512];
__device__ float g_cB[(size_t)BATCH*NCHUNK*512];
__device__ float g_cr[(size_t)BATCH*NCHUNK*512];
__device__ float g_spl[512];
// transposed split weights [N, K] fp16 hi/lo
__device__ h16 g_wtin_hi[1024*256], g_wtin_lo[1024*256];
__device__ h16 g_wtg_hi [1024*512], g_wtg_lo [1024*512];
__device__ h16 g_wto_hi [256*512],  g_wto_lo [256*512];
__device__ h16 g_wtf1_hi[1024*256], g_wtf1_lo[1024*256];
__device__ h16 g_wtf2_hi[256*1024], g_wtf2_lo[256*1024];

__device__ __forceinline__ float sigmoidf_(float x) { return 1.f / (1.f + expf(-x)); }
__device__ __forceinline__ float siluf_(float x)    { return x / (1.f + expf(-x)); }

__device__ __forceinline__ uint32_t smem_u32(const void* p) {
    uint32_t a;
    asm("{ .reg .u64 t; cvta.to.shared.u64 t, %1; cvt.u32.u64 %0, t; }" : "=r"(a) : "l"(p));
    return a;
}
__device__ __forceinline__ void ldsm_x4(uint32_t* r, uint32_t addr) {
    asm volatile("ldmatrix.sync.aligned.m8n8.x4.shared.b16 {%0,%1,%2,%3}, [%4];"
                 : "=r"(r[0]), "=r"(r[1]), "=r"(r[2]), "=r"(r[3]) : "r"(addr));
}
__device__ __forceinline__ void mma16816(float* c, const uint32_t* a, const uint32_t* b) {
    asm volatile("mma.sync.aligned.m16n8k16.row.col.f32.f16.f16.f32 "
                 "{%0,%1,%2,%3}, {%4,%5,%6,%7}, {%8,%9}, {%0,%1,%2,%3};"
                 : "+f"(c[0]), "+f"(c[1]), "+f"(c[2]), "+f"(c[3])
                 : "r"(a[0]), "r"(a[1]), "r"(a[2]), "r"(a[3]), "r"(b[0]), "r"(b[1]));
}
__device__ __forceinline__ void cpa16(uint32_t dst, const void* src) {
    asm volatile("cp.async.cg.shared.global [%0], [%1], 16;" :: "r"(dst), "l"(src));
}
#define CP_COMMIT() asm volatile("cp.async.commit_group;" ::: "memory")
#define CP_WAIT(n)  asm volatile("cp.async.wait_group %0;" :: "n"(n) : "memory")

// ---------------- fp16 mma GEMM with W hi/lo split, cp.async double buffer ----
// C[M,N] = A[M,K] @ (Wh+Wl)[N,K]^T ; block 128x128x32, 8 warps, warp 32x64.
#define BM 128
#define BN 128
#define BK 32
#define PADH 40                       // halfs per smem row (80 B, 16B-aligned)
#define STG (BM*PADH*2)               // 10240 B per matrix per stage
#define GEMM_SMEM (6*STG)             // 61440 B

__global__ void __launch_bounds__(256, 1)
gemm_fp16(const h16* __restrict__ A, const h16* __restrict__ Bhw, const h16* __restrict__ Blw,
          int K, float* __restrict__ Cf, h16* __restrict__ Ch,
          int ldc, const float* __restrict__ bias, int act)
{
    extern __shared__ __align__(16) char smem[];
    const uint32_t sb = smem_u32(smem);
    const uint32_t uA  = sb;             // [2][128][PADH]
    const uint32_t uBh = sb + 2*STG;
    const uint32_t uBl = sb + 4*STG;

    const int tid = threadIdx.x, wid = tid >> 5, lane = tid & 31;
    const int bx = blockIdx.x, by = blockIdx.y;
    const int warp_m = wid & 3, warp_n = wid >> 2;

    const h16* gA  = A   + (size_t)(by * BM) * K;
    const h16* gBh = Bhw + (size_t)(bx * BN) * K;
    const h16* gBl = Blw + (size_t)(bx * BN) * K;

    // per-thread load slots: 2 x 16B per matrix per chunk
    const int r0 = tid >> 2, c0 = (tid & 3);          // slot tid
    const int r1 = (tid + 256) >> 2, c1 = ((tid + 256) & 3);

    float c[2][8][4];
    #pragma unroll
    for (int mt = 0; mt < 2; mt++)
        #pragma unroll
        for (int nt = 0; nt < 8; nt++)
            #pragma unroll
            for (int j = 0; j < 4; j++) c[mt][nt][j] = 0.f;

    const int a_row = (lane & 15);
    const int a_kof = (lane >> 4) * 8;
    const int b_rof = ((lane >> 4) & 1) * 8 + (lane & 7);
    const int b_kof = ((lane >> 3) & 1) * 8;

    const int nchunk = K / BK;

    // load chunk `ch` into stage `st`
    auto load_chunk = [&](int ch, int st) {
        const int k0 = ch * BK;
        uint32_t dA = uA  + st*STG;
        uint32_t dH = uBh + st*STG;
        uint32_t dL = uBl + st*STG;
        cpa16(dA + r0*80 + c0*16, gA  + (size_t)r0*K + k0 + c0*8);
        cpa16(dA + r1*80 + c1*16, gA  + (size_t)r1*K + k0 + c1*8);
        cpa16(dH + r0*80 + c0*16, gBh + (size_t)r0*K + k0 + c0*8);
        cpa16(dH + r1*80 + c1*16, gBh + (size_t)r1*K + k0 + c1*8);
        cpa16(dL + r0*80 + c0*16, gBl + (size_t)r0*K + k0 + c0*8);
        cpa16(dL + r1*80 + c1*16, gBl + (size_t)r1*K + k0 + c1*8);
    };

    load_chunk(0, 0);
    CP_COMMIT();

    for (int ch = 0; ch < nchunk; ch++) {
        const int st = ch & 1;
        if (ch + 1 < nchunk) {
            load_chunk(ch + 1, (ch + 1) & 1);
            CP_COMMIT();
            CP_WAIT(1);
        } else {
            CP_WAIT(0);
        }
        __syncthreads();

        const uint32_t bA  = uA  + st*STG;
        const uint32_t bBh = uBh + st*STG;
        const uint32_t bBl = uBl + st*STG;

        #pragma unroll
        for (int ks = 0; ks < 2; ks++) {
            const int kc = ks * 16;
            uint32_t ah[2][4];
            #pragma unroll
            for (int mt = 0; mt < 2; mt++) {
                int row = warp_m * 32 + mt * 16 + a_row;
                ldsm_x4(ah[mt], bA + (uint32_t)(row * PADH + kc + a_kof) * 2);
            }
            uint32_t bh[8][2], bl[8][2];
            #pragma unroll
            for (int np = 0; np < 4; np++) {
                int rown = warp_n * 64 + np * 16 + b_rof;
                uint32_t off = (uint32_t)(rown * PADH + kc + b_kof) * 2;
                uint32_t r[4];
                ldsm_x4(r, bBh + off);
                bh[np*2][0] = r[0]; bh[np*2][1] = r[1];
                bh[np*2+1][0] = r[2]; bh[np*2+1][1] = r[3];
                ldsm_x4(r, bBl + off);
                bl[np*2][0] = r[0]; bl[np*2][1] = r[1];
                bl[np*2+1][0] = r[2]; bl[np*2+1][1] = r[3];
            }
            #pragma unroll
            for (int mt = 0; mt < 2; mt++)
                #pragma unroll
                for (int nt = 0; nt < 8; nt++) {
                    mma16816(c[mt][nt], ah[mt], bh[nt]);
                    mma16816(c[mt][nt], ah[mt], bl[nt]);
                }
        }
        __syncthreads();
    }

    // epilogue
    const int row00 = by * BM + warp_m * 32 + (lane >> 2);
    const int col00 = bx * BN + warp_n * 64 + (lane & 3) * 2;
    #pragma unroll
    for (int mt = 0; mt < 2; mt++) {
        #pragma unroll
        for (int nt = 0; nt < 8; nt++) {
            const int col = col00 + nt * 8;
            #pragma unroll
            for (int half = 0; half < 2; half++) {
                const int row = row00 + mt * 16 + half * 8;
                float v0 = c[mt][nt][half*2+0];
                float v1 = c[mt][nt][half*2+1];
                if (bias) { v0 += bias[col]; v1 += bias[col+1]; }
                if (act)  { v0 = siluf_(v0); v1 = siluf_(v1); }
                if (Cf) {
                    float2 q; q.x = v0; q.y = v1;
                    *(float2*)(Cf + (size_t)row * ldc + col) = q;
                } else {
                    __half2 hp; hp.x = __float2half_rn(v0); hp.y = __float2half_rn(v1);
                    *(__half2*)(Ch + (size_t)row * ldc + col) = hp;
                }
            }
        }
    }
}

// ---------------- weight prep: T[n,k] = W[k,n], fp16 hi/lo ----------------
__global__ void wprep_kernel(const float* __restrict__ W, int K, int N,
                             h16* __restrict__ Thi, h16* __restrict__ Tlo)
{
    int idx = blockIdx.x * blockDim.x + threadIdx.x;
    if (idx >= N * K) return;
    int n = idx / K, k = idx - n * K;
    float v = W[(size_t)k * N + n];
    h16 hi = __float2half_rn(v);
    Thi[idx] = hi;
    Tlo[idx] = __float2half_rn(v - __half2float(hi));
}

// ---------------- x -> fp16 ----------------
__global__ void xhalf_kernel(const float* __restrict__ x)
{
    size_t idx = (size_t)blockIdx.x * blockDim.x + threadIdx.x;
    if (idx >= (size_t)ROWS * 256) return;
    g_x16[idx] = __float2half_rn(x[idx]);
}

// ---------------- softplus(Lambda) table ----------------
__global__ void splam_kernel(const float* __restrict__ L)
{
    int i = blockIdx.x * blockDim.x + threadIdx.x;
    if (i < 512) g_spl[i] = log1pf(expf(L[i]));
}

// ---------------- conv (K=4) + bias + silu -> xc fp16 ----------------
__global__ void conv_kernel(const float* __restrict__ conv_w, const float* __restrict__ conv_b)
{
    size_t idx = (size_t)blockIdx.x * blockDim.x + threadIdx.x;
    if (idx >= (size_t)ROWS * 512) return;
    size_t row = idx >> 9;
    int c = (int)(idx & 511);
    int t = (int)(row & (SEQ - 1));
    const float* w = conv_w + c * KSIZE;
    const h16* xb = g_xz + row * 1024 + c;
    float acc = conv_b[c];
    if (t >= 3) {
        acc = fmaf(__half2float(xb[-3*1024]), w[0], acc);
        acc = fmaf(__half2float(xb[-2*1024]), w[1], acc);
        acc = fmaf(__half2float(xb[-1*1024]), w[2], acc);
        acc = fmaf(__half2float(xb[0]),       w[3], acc);
    } else {
        #pragma unroll
        for (int k = 0; k < KSIZE; k++)
            if (t - (KSIZE-1) + k >= 0)
                acc = fmaf(__half2float(xb[(ptrdiff_t)(k - (KSIZE-1)) * 1024]), w[k], acc);
    }
    float s = acc * sigmoidf_(acc);
    g_xc[idx] = __float2half_rn(s);
}

// ---------------- gates -> alpha, beta' (fp32) ----------------
__global__ void gate_kernel()
{
    size_t idx = (size_t)blockIdx.x * blockDim.x + threadIdx.x;
    if (idx >= (size_t)ROWS * 512) return;
    size_t row = idx >> 9;
    int c = (int)(idx & 511);
    float rec = g_gates[row * 1024 + c];
    float inp = g_gates[row * 1024 + 512 + c];
    float xc = __half2float(g_xc[idx]);
    float alpha = expf(-g_spl[c] * sigmoidf_(rec));
    float beta = sqrtf(fmaf(-alpha, alpha, 1.f + 1e-8f)) * sigmoidf_(inp);
    g_a[idx] = alpha;
    g_b[idx] = beta * xc;
}

// ---------------- chunked scan ----------------
__global__ void scan_p1_kernel()
{
    int idx = blockIdx.x * blockDim.x + threadIdx.x;
    if (idx >= BATCH * NCHUNK * 512) return;
    int c = idx & 511;
    int rest = idx >> 9;
    int chunk = rest & (NCHUNK - 1);
    int b = rest / NCHUNK;
    size_t base = ((size_t)b * SEQ + (size_t)chunk * CLEN) * 512 + c;
    float A = 1.f, Bv = 0.f;
    #pragma unroll 8
    for (int i = 0; i < CLEN; i++) {
        size_t off = base + (size_t)i * 512;
        float a = g_a[off], bb = g_b[off];
        A *= a;
        Bv = fmaf(a, Bv, bb);
    }
    g_cA[idx] = A;
    g_cB[idx] = Bv;
}
__global__ void scan_p2_kernel()
{
    int idx = blockIdx.x * blockDim.x + threadIdx.x;
    if (idx >= BATCH * 512) return;
    int c = idx & 511;
    int b = idx >> 9;
    float carry = 0.f;
    for (int chunk = 0; chunk < NCHUNK; chunk++) {
        int cidx = ((b * NCHUNK + chunk) << 9) + c;
        g_cr[cidx] = carry;
        carry = fmaf(g_cA[cidx], carry, g_cB[cidx]);
    }
}
__global__ void scan_p3_kernel()
{
    int idx = blockIdx.x * blockDim.x + threadIdx.x;
    if (idx >= BATCH * NCHUNK * 512) return;
    int c = idx & 511;
    int rest = idx >> 9;
    int chunk = rest & (NCHUNK - 1);
    int b = rest / NCHUNK;
    size_t rowbase = (size_t)b * SEQ + (size_t)chunk * CLEN;
    size_t base = rowbase * 512 + c;
    const h16* zp = g_xz + rowbase * 1024 + 512 + c;
    float h = g_cr[idx];
    #pragma unroll 4
    for (int i = 0; i < CLEN; i++) {
        size_t off = base + (size_t)i * 512;
        h = fmaf(g_a[off], h, g_b[off]);
        float z = __half2float(zp[(size_t)i * 1024]);
        g_u[off] = __float2half_rn(siluf_(z) * h);
    }
}

// ---------------- LayerNorm(a+b), optional fp16 out ----------------
__global__ void ln_kernel(const float* __restrict__ a, const float* __restrict__ b,
                          const float* __restrict__ gamma, const float* __restrict__ beta,
                          float* __restrict__ out, h16* __restrict__ o16)
{
    int warp = (int)((blockIdx.x * blockDim.x + threadIdx.x) >> 5);
    int lane = threadIdx.x & 31;
    if (warp >= ROWS) return;
    size_t base = (size_t)warp * 256;
    float v[8];
    float s = 0.f, s2 = 0.f;
    #pragma unroll
    for (int i = 0; i < 8; i++) {
        int col = lane + i * 32;
        float x = a[base + col] + b[base + col];
        v[i] = x;
        s += x;
        s2 = fmaf(x, x, s2);
    }
    #pragma unroll
    for (int o = 16; o; o >>= 1) {
        s  += __shfl_xor_sync(0xffffffffu, s,  o);
        s2 += __shfl_xor_sync(0xffffffffu, s2, o);
    }
    float mean = s * (1.f / 256.f);
    float var  = s2 * (1.f / 256.f) - mean * mean;
    float inv  = rsqrtf(var + 1e-12f);
    #pragma unroll
    for (int i = 0; i < 8; i++) {
        int col = lane + i * 32;
        float y = (v[i] - mean) * inv * gamma[col] + beta[col];
        out[base + col] = y;
        if (o16) o16[base + col] = __float2half_rn(y);
    }
}

// ---------------- launcher ----------------
extern "C" void kernel_launch(void* const* d_in, const int* in_sizes, int n_in,
                              void* d_out, int out_size)
{
    const float* x       = (const float*)d_in[0];
    const float* w_in    = (const float*)d_in[1];
    const float* conv_w  = (const float*)d_in[2];
    const float* conv_b  = (const float*)d_in[3];
    const float* w_gates = (const float*)d_in[4];
    const float* b_gates = (const float*)d_in[5];
    const float* Lambda  = (const float*)d_in[6];
    const float* w_out   = (const float*)d_in[7];
    const float* ln1_g   = (const float*)d_in[8];
    const float* ln1_b   = (const float*)d_in[9];
    const float* ffn_w1  = (const float*)d_in[10];
    const float* ffn_b1  = (const float*)d_in[11];
    const float* ffn_w2  = (const float*)d_in[12];
    const float* ffn_b2  = (const float*)d_in[13];
    const float* ln2_g   = (const float*)d_in[14];
    const float* ln2_b   = (const float*)d_in[15];
    float* out = (float*)d_out;

    cudaFuncSetAttribute(gemm_fp16, cudaFuncAttributeMaxDynamicSharedMemorySize, GEMM_SMEM);

    #define SYM(p, s) float* p; cudaGetSymbolAddress((void**)&p, s)
    #define SYMH(p, s) h16* p; cudaGetSymbolAddress((void**)&p, s)
    SYM(p_gates, g_gates); SYM(p_rec, g_rec); SYM(p_hs, g_hs); SYM(p_ff, g_ff);
    SYMH(p_xz, g_xz);   SYMH(p_xc, g_xc);  SYMH(p_u, g_u);
    SYMH(p_x16, g_x16); SYMH(p_hs16, g_hs16); SYMH(p_f1, g_f1);
    SYMH(p_wtin_hi, g_wtin_hi); SYMH(p_wtin_lo, g_wtin_lo);
    SYMH(p_wtg_hi,  g_wtg_hi);  SYMH(p_wtg_lo,  g_wtg_lo);
    SYMH(p_wto_hi,  g_wto_hi);  SYMH(p_wto_lo,  g_wto_lo);
    SYMH(p_wtf1_hi, g_wtf1_hi); SYMH(p_wtf1_lo, g_wtf1_lo);
    SYMH(p_wtf2_hi, g_wtf2_hi); SYMH(p_wtf2_lo, g_wtf2_lo);

    const int ew512 = (int)(((size_t)ROWS * 512 + 255) / 256);
    const int ew256 = (int)(((size_t)ROWS * 256 + 255) / 256);
    const int ch_blocks = (BATCH * NCHUNK * 512 + 255) / 256;

    // weight prep (W is [K,N] row-major -> T[N][K] fp16 hi/lo)
    wprep_kernel<<<(1024*256+255)/256, 256>>>(w_in,    256,  1024, p_wtin_hi, p_wtin_lo);
    wprep_kernel<<<(1024*512+255)/256, 256>>>(w_gates, 512,  1024, p_wtg_hi,  p_wtg_lo);
    wprep_kernel<<<(256*512 +255)/256, 256>>>(w_out,   512,  256,  p_wto_hi,  p_wto_lo);
    wprep_kernel<<<(1024*256+255)/256, 256>>>(ffn_w1,  256,  1024, p_wtf1_hi, p_wtf1_lo);
    wprep_kernel<<<(256*1024+255)/256, 256>>>(ffn_w2,  1024, 256,  p_wtf2_hi, p_wtf2_lo);
    xhalf_kernel<<<ew256, 256>>>(x);
    splam_kernel<<<2, 256>>>(Lambda);

    const dim3 gN1024(1024 / BN, ROWS / BM);
    const dim3 gN256 (256  / BN, ROWS / BM);

    // GEMM1: xz = x @ w_in  (fp16 out), K=256
    gemm_fp16<<<gN1024, 256, GEMM_SMEM>>>(p_x16, p_wtin_hi, p_wtin_lo, 256,
                                          nullptr, p_xz, 1024, nullptr, 0);
    conv_kernel<<<ew512, 256>>>(conv_w, conv_b);
    // GEMM2: gates = xc @ w_gates + b_gates (fp32 out), K=512
    gemm_fp16<<<gN1024, 256, GEMM_SMEM>>>(p_xc, p_wtg_hi, p_wtg_lo, 512,
                                          p_gates, nullptr, 1024, b_gates, 0);
    gate_kernel<<<ew512, 256>>>();
    scan_p1_kernel<<<ch_blocks, 256>>>();
    scan_p2_kernel<<<(BATCH*512 + 255)/256, 256>>>();
    scan_p3_kernel<<<ch_blocks, 256>>>();
    // GEMM3: rec = u @ w_out (fp32 out), K=512
    gemm_fp16<<<gN256, 256, GEMM_SMEM>>>(p_u, p_wto_hi, p_wto_lo, 512,
                                         p_rec, nullptr, 256, nullptr, 0);
    // LN1: hs = LN(rec + x), fp32 + fp16
    ln_kernel<<<ROWS/8, 256>>>(p_rec, x, ln1_g, ln1_b, p_hs, p_hs16);
    // GEMM4: f1 = silu(hs @ ffn_w1 + b1) (fp16 out), K=256
    gemm_fp16<<<gN1024, 256, GEMM_SMEM>>>(p_hs16, p_wtf1_hi, p_wtf1_lo, 256,
                                          nullptr, p_f1, 1024, ffn_b1, 1);
    // GEMM5: ff = f1 @ ffn_w2 + b2 (fp32 out), K=1024
    gemm_fp16<<<gN256, 256, GEMM_SMEM>>>(p_f1, p_wtf2_hi, p_wtf2_lo, 1024,
                                         p_ff, nullptr, 256, ffn_b2, 0);
    // LN2: out = LN(ff + hs)
    ln_kernel<<<ROWS/8, 256>>>(p_ff, p_hs, ln2_g, ln2_b, out, nullptr);
}